// round 9
// baseline (speedup 1.0000x reference)
#include <cuda_runtime.h>
#include <cuda_bf16.h>
#include <cstdint>

#define Bb 8
#define Nn 1024
#define Ee 10
#define EPAD 16
#define NCH 32

__device__ float g_Ppart[Bb * NCH * Nn];
__device__ float g_Mpart[Bb * NCH * Nn];
__device__ float g_base[Bb * Nn * Ee];
__device__ __nv_bfloat16 g_Abf[(size_t)Bb * Nn * Nn];    // A in bf16 (loop-invariant)
__device__ __nv_bfloat16 g_hbf[2][Bb * EPAD * Nn];       // h ping-pong [b][e(pad16)][i]
__device__ float g_S[Bb * Ee];
__device__ float g_wp[Ee * Ee];

__device__ __forceinline__ uint32_t smem_u32(const void* p) {
    uint32_t a;
    asm("{ .reg .u64 t; cvta.to.shared.u64 t, %1; cvt.u32.u64 %0, t; }"
        : "=r"(a) : "l"(p));
    return a;
}

#define LDMX4(r0, r1, r2, r3, addr)                                           \
    asm volatile("ldmatrix.sync.aligned.m8n8.x4.shared.b16 {%0,%1,%2,%3}, [%4];" \
        : "=r"(r0), "=r"(r1), "=r"(r2), "=r"(r3) : "r"(addr))

__device__ __forceinline__ void mma_bf16(float* c, uint32_t a0, uint32_t a1,
                                         uint32_t a2, uint32_t a3,
                                         uint32_t b0, uint32_t b1) {
    asm volatile(
        "mma.sync.aligned.m16n8k16.row.col.f32.bf16.bf16.f32 "
        "{%0,%1,%2,%3}, {%4,%5,%6,%7}, {%8,%9}, {%0,%1,%2,%3};"
        : "+f"(c[0]), "+f"(c[1]), "+f"(c[2]), "+f"(c[3])
        : "r"(a0), "r"(a1), "r"(a2), "r"(a3), "r"(b0), "r"(b1));
}

// ---------------------------------------------------------------------------
// Convert A -> bf16 once.
// ---------------------------------------------------------------------------
__global__ void __launch_bounds__(256) conv_kernel(const float4* __restrict__ A) {
    size_t idx = (size_t)blockIdx.x * 256 + threadIdx.x;   // one uint4 (8 bf16)
    float4 v0 = A[2 * idx], v1 = A[2 * idx + 1];
    __nv_bfloat162 p0 = __floats2bfloat162_rn(v0.x, v0.y);
    __nv_bfloat162 p1 = __floats2bfloat162_rn(v0.z, v0.w);
    __nv_bfloat162 p2 = __floats2bfloat162_rn(v1.x, v1.y);
    __nv_bfloat162 p3 = __floats2bfloat162_rn(v1.z, v1.w);
    uint4 o;
    o.x = *reinterpret_cast<uint32_t*>(&p0);
    o.y = *reinterpret_cast<uint32_t*>(&p1);
    o.z = *reinterpret_cast<uint32_t*>(&p2);
    o.w = *reinterpret_cast<uint32_t*>(&p3);
    reinterpret_cast<uint4*>(g_Abf)[idx] = o;
}

// ---------------------------------------------------------------------------
// Colsum: P/M column sums of weights; stages Wp.
// ---------------------------------------------------------------------------
__global__ void __launch_bounds__(256) colsum_kernel(
    const float4* __restrict__ w4, const float* __restrict__ wp)
{
    int i4 = threadIdx.x, jc = blockIdx.x, b = blockIdx.y;
    if (jc == 0 && b == 0 && threadIdx.x < Ee * Ee)
        g_wp[threadIdx.x] = wp[threadIdx.x];

    const float4* p = w4 + ((size_t)(b * Nn + jc * 32) * 256) + i4;
    float4 sp = make_float4(0.f, 0.f, 0.f, 0.f);
    float4 sm = make_float4(0.f, 0.f, 0.f, 0.f);
#pragma unroll 8
    for (int j = 0; j < 32; j++) {
        float4 v = p[(size_t)j * 256];
        sp.x += fmaxf(v.x, 0.f); sm.x += fminf(v.x, 0.f);
        sp.y += fmaxf(v.y, 0.f); sm.y += fminf(v.y, 0.f);
        sp.z += fmaxf(v.z, 0.f); sm.z += fminf(v.z, 0.f);
        sp.w += fmaxf(v.w, 0.f); sm.w += fminf(v.w, 0.f);
    }
    ((float4*)g_Ppart)[(b * NCH + jc) * 256 + i4] = sp;
    ((float4*)g_Mpart)[(b * NCH + jc) * 256 + i4] = sm;
}

// ---------------------------------------------------------------------------
// Base: base[b,i,e], emb1=relu(base), h1=Wp@emb1 -> g_hbf[0]; zero pads.
// ---------------------------------------------------------------------------
__global__ void __launch_bounds__(256) base_kernel(
    const float* __restrict__ feat,
    const float* __restrict__ ws,
    const float* __restrict__ wnb,
    const float* __restrict__ ew)
{
    int idx = blockIdx.x * 256 + threadIdx.x;
    int b = idx >> 10, i = idx & 1023;
    if (idx < Bb * Ee) g_S[idx] = 0.f;

    float P = 0.f, M = 0.f;
#pragma unroll 8
    for (int c = 0; c < NCH; c++) {
        P += g_Ppart[(b * NCH + c) * Nn + i];
        M += g_Mpart[(b * NCH + c) * Nn + i];
    }
    float f = feat[idx];

    float ewv[Ee];
#pragma unroll
    for (int e = 0; e < Ee; e++) ewv[e] = ew[e];

    float emb1[Ee];
#pragma unroll
    for (int e = 0; e < Ee; e++) {
        float cP = 0.f, cM = 0.f;
#pragma unroll
        for (int g = 0; g < Ee; g++) {
            float wv = wnb[e * Ee + g];
            cP += wv * fmaxf(ewv[g], 0.f);
            cM += wv * fminf(ewv[g], 0.f);
        }
        float basev = f * ws[e] + cP * P + cM * M;
        g_base[idx * Ee + e] = basev;
        emb1[e] = fmaxf(basev, 0.f);
    }
#pragma unroll
    for (int e = 0; e < Ee; e++) {
        float hv = 0.f;
#pragma unroll
        for (int g = 0; g < Ee; g++) hv += g_wp[e * Ee + g] * emb1[g];
        g_hbf[0][(b * EPAD + e) * Nn + i] = __float2bfloat16_rn(hv);
    }
#pragma unroll
    for (int e = Ee; e < EPAD; e++) {
        g_hbf[0][(b * EPAD + e) * Nn + i] = __float2bfloat16_rn(0.f);
        g_hbf[1][(b * EPAD + e) * Nn + i] = __float2bfloat16_rn(0.f);
    }
}

// ---------------------------------------------------------------------------
// Iteration via mma.sync (HMMA bf16):
//   C[64,16] = A_rows[64,1024] @ h^T; fused epilogue.
// CTA = 128 thr (4 warps, 16 rows each). grid (16, 8) = 128 CTAs.
// h^T (B operand, 16x1024) staged swizzled in smem; A in 16 x 8KB chunks,
// double-buffered through registers. 16-byte XOR swizzle -> conflict-free
// ldmatrix for both operands.
// ---------------------------------------------------------------------------
__global__ void __launch_bounds__(128) iter_kernel(int src,
                                                   float* __restrict__ emb_out,
                                                   int last)
{
    __shared__ __align__(16) __nv_bfloat16 hs[16 * 1024];  // 32 KB
    __shared__ __align__(16) __nv_bfloat16 as[64 * 64];    // 8 KB (reused as C)
    __shared__ float wps[Ee * Ee];
    __shared__ float sacc[Ee];
    int rb = blockIdx.x, b = blockIdx.y;
    int tid = threadIdx.x;

    // stage h^T swizzled: hs[e][u^(e&7)] = h[e][u]  (u = 16B unit)
    const uint4* hb4 = (const uint4*)(g_hbf[src] + (size_t)b * EPAD * Nn);
    uint4* hs4 = (uint4*)hs;
#pragma unroll
    for (int q = 0; q < 16; q++) {
        int idx = tid + q * 128;
        int e = idx >> 7, u = idx & 127;
        hs4[e * 128 + (u ^ (e & 7))] = hb4[idx];
    }
    if (tid < Ee * Ee) wps[tid] = g_wp[tid];
    if (tid < Ee) sacc[tid] = 0.f;

    const uint4* Ag = (const uint4*)(g_Abf + ((size_t)b * Nn + rb * 64) * Nn);
    uint4* as4 = (uint4*)as;

    // preload chunk 0
    uint4 v[4];
#pragma unroll
    for (int p = 0; p < 4; p++) {
        int idx = tid + p * 128;
        int r = idx >> 3, u = idx & 7;
        v[p] = Ag[(size_t)r * 128 + u];
    }
    __syncthreads();                    // hs staged
#pragma unroll
    for (int p = 0; p < 4; p++) {
        int idx = tid + p * 128;
        int r = idx >> 3, u = idx & 7;
        as4[r * 8 + (u ^ (r & 7))] = v[p];
    }
    __syncthreads();

    int lane = tid & 31, w = tid >> 5;
    int half = lane >> 4, lr = lane & 15, l7 = lane & 7;
    uint32_t a_row = smem_u32(as) + (uint32_t)(w * 16 + lr) * 128;
    uint32_t b_row = smem_u32(hs) + (uint32_t)lr * 2048;

    float c0[4] = {0.f, 0.f, 0.f, 0.f};
    float c1[4] = {0.f, 0.f, 0.f, 0.f};

    for (int c = 0; c < 16; c++) {
        if (c < 15) {
#pragma unroll
            for (int p = 0; p < 4; p++) {
                int idx = tid + p * 128;
                int r = idx >> 3, u = idx & 7;
                v[p] = Ag[(size_t)r * 128 + (c + 1) * 8 + u];
            }
        }
#pragma unroll
        for (int s = 0; s < 4; s++) {
            int sg = c * 4 + s;
            uint32_t aaddr = a_row + (uint32_t)(((2 * s + half) ^ l7) << 4);
            uint32_t baddr = b_row + (uint32_t)(((2 * sg + half) ^ l7) << 4);
            uint32_t a0, a1, a2, a3, r0, r1, r2, r3;
            LDMX4(a0, a1, a2, a3, aaddr);
            LDMX4(r0, r1, r2, r3, baddr);
            mma_bf16(c0, a0, a1, a2, a3, r0, r2);   // cols 0-7
            mma_bf16(c1, a0, a1, a2, a3, r1, r3);   // cols 8-15
        }
        __syncthreads();
        if (c < 15) {
#pragma unroll
            for (int p = 0; p < 4; p++) {
                int idx = tid + p * 128;
                int r = idx >> 3, u = idx & 7;
                as4[r * 8 + (u ^ (r & 7))] = v[p];
            }
            __syncthreads();
        }
    }

    // dump C fragments to smem (reuse as: float cs[64][16])
    float* cs = (float*)as;
    {
        int g = lane >> 2, t = lane & 3;
        int rlo = w * 16 + g, rhi = rlo + 8;
        cs[rlo * 16 + 2 * t] = c0[0];     cs[rlo * 16 + 2 * t + 1] = c0[1];
        cs[rhi * 16 + 2 * t] = c0[2];     cs[rhi * 16 + 2 * t + 1] = c0[3];
        cs[rlo * 16 + 8 + 2 * t] = c1[0]; cs[rlo * 16 + 8 + 2 * t + 1] = c1[1];
        cs[rhi * 16 + 8 + 2 * t] = c1[2]; cs[rhi * 16 + 8 + 2 * t + 1] = c1[3];
    }
    __syncthreads();

    if (tid < 64) {
        int i = rb * 64 + tid;
        const float* bp = g_base + ((size_t)(b * Nn) + i) * Ee;
        float embv[Ee];
#pragma unroll
        for (int e = 0; e < Ee; e++)
            embv[e] = fmaxf(bp[e] + cs[tid * 16 + e], 0.f);

        __nv_bfloat16* ho = g_hbf[src ^ 1] + (size_t)b * EPAD * Nn + i;
#pragma unroll
        for (int e = 0; e < Ee; e++) {
            float hv = 0.f;
#pragma unroll
            for (int f = 0; f < Ee; f++) hv = fmaf(wps[e * Ee + f], embv[f], hv);
            ho[(size_t)e * Nn] = __float2bfloat16_rn(hv);
        }
        if (last) {
#pragma unroll
            for (int e = 0; e < Ee; e++) {
                emb_out[((size_t)(b * Nn) + i) * Ee + e] = embv[e];
                atomicAdd(&sacc[e], embv[e]);
            }
        }
    }
    if (last) {
        __syncthreads();
        if (tid < Ee) atomicAdd(&g_S[b * Ee + tid], sacc[tid]);
    }
}

// ---------------------------------------------------------------------------
// Final: q[b,i] = c_b + sum_e d_e * emb[b,i,e]
// ---------------------------------------------------------------------------
__global__ void __launch_bounds__(128) final_kernel(
    const float* __restrict__ emb,
    float* __restrict__ q,
    const float* __restrict__ wqr,
    const float* __restrict__ wall,
    const float* __restrict__ wact)
{
    int idx = blockIdx.x * 128 + threadIdx.x;
    int b = idx >> 10;
    float cb = 0.f;
#pragma unroll
    for (int f = 0; f < Ee; f++) {
        float t = 0.f;
#pragma unroll
        for (int e = 0; e < Ee; e++) t += wall[f * Ee + e] * g_S[b * Ee + e];
        cb += wqr[f] * t;
    }
    float qv = cb;
#pragma unroll
    for (int e = 0; e < Ee; e++) {
        float t = 0.f;
#pragma unroll
        for (int f = 0; f < Ee; f++) t += wqr[Ee + f] * wact[f * Ee + e];
        qv += t * emb[(size_t)idx * Ee + e];
    }
    q[idx] = qv;
}

extern "C" void kernel_launch(void* const* d_in, const int* in_sizes, int n_in,
                              void* d_out, int out_size) {
    const float* features       = (const float*)d_in[0];
    const float* weights        = (const float*)d_in[1];
    const float* adjacency      = (const float*)d_in[2];
    const float* w_selected     = (const float*)d_in[3];
    const float* w_nbpriors     = (const float*)d_in[4];
    const float* w_nbweights    = (const float*)d_in[5];
    const float* w_nbweights_ew = (const float*)d_in[6];
    const float* w_q_reduc      = (const float*)d_in[7];
    const float* w_q_allembed   = (const float*)d_in[8];
    const float* w_q_action     = (const float*)d_in[9];

    float* out = (float*)d_out;
    float* q = out;                  // [B,N]
    float* emb_out = out + Bb * Nn;  // [B,N,E]

    conv_kernel<<<4096, 256>>>((const float4*)adjacency);
    colsum_kernel<<<dim3(NCH, Bb), 256>>>((const float4*)weights, w_nbpriors);
    base_kernel<<<32, 256>>>(features, w_selected, w_nbweights, w_nbweights_ew);

    dim3 ig(16, Bb);                 // 128 CTAs
    iter_kernel<<<ig, 128>>>(0, emb_out, 0);  // iter 2
    iter_kernel<<<ig, 128>>>(1, emb_out, 0);  // iter 3
    iter_kernel<<<ig, 128>>>(0, emb_out, 0);  // iter 4
    iter_kernel<<<ig, 128>>>(1, emb_out, 1);  // iter 5 (last)

    final_kernel<<<64, 128>>>(emb_out, q, w_q_reduc, w_q_allembed, w_q_action);
}